// round 14
// baseline (speedup 1.0000x reference)
#include <cuda_runtime.h>
#include <cuda_bf16.h>
#include <cuda_fp16.h>
#include <cstdint>

#define N_NODES 100000
#define N_EDGES 1280000
#define D 64
#define TC_BLOCKS 782         // ceil(100000 / 128)
#define PITCH 72              // smem row pitch in bf16 (144B) -> conflict-free frags
#define SORT_BLOCKS 148
#define EDGE_CHUNK 8656       // multiple of 16; 148*8656 >= N_EDGES
#define NODE_CHUNK 676        // ceil(100000 / 148)

// ---------------------------------------------------------------------------
// Scratch (__device__ globals; zero-initialized at module load)
__device__ uint4  g_y4u[N_NODES * 8];   // x @ W_l^T in fp16 (8 halves per uint4)
__device__ uint4  g_r4u[N_NODES * 8];   // x @ W_r^T + b in fp16 (8 halves/uint4)
__device__ float4 g_h4[N_NODES * 16];   // layer-1 output (fp32)
__device__ int    g_hist[N_NODES];      // re-zeroed by gather L1
__device__ int    g_rank[N_EDGES];      // per-edge slot within its dst segment
__device__ int    g_off[N_NODES + 1];
__device__ int    g_srcsorted[N_EDGES];
__device__ int    g_bsum[SORT_BLOCKS];
__device__ volatile int g_bar_count;    // re-zeroed by gather L1
// Pre-split weights: rows n: n<64 -> Wl[n], n>=64 -> Wr[n-64]; [layer][n*64+k]
__device__ __nv_bfloat16 g_Bh[2][128 * 64];
__device__ __nv_bfloat16 g_Bl[2][128 * 64];

// ---------------------------------------------------------------------------
// Warp-uniform edge dtype probe: int64 interp valid iff 32 samples in range.
__device__ __forceinline__ int detect64(const void* ei) {
    const long long* p = (const long long*)ei;
    int lane = threadIdx.x & 31;
    long long v = __ldg(&p[lane * 317]);
    return __all_sync(0xFFFFFFFFu, v >= 0 && v < N_NODES);
}

// Grid barrier for the persistent sort kernel (148 blocks = 1/SM, co-resident).
__device__ __forceinline__ void grid_bar(int target) {
    __syncthreads();
    if (threadIdx.x == 0) {
        __threadfence();
        atomicAdd((int*)&g_bar_count, 1);
        while (g_bar_count < target) { }
        __threadfence();
    }
    __syncthreads();
}

// ---------------------------------------------------------------------------
// Fused counting sort: hist+rank -> scan -> place. One launch, grid barriers.
__global__ __launch_bounds__(256) void sort_kernel(const void* __restrict__ ei) {
    __shared__ int s_is64;
    __shared__ int warp_sums[8];
    __shared__ int s_base;

    const int tid = threadIdx.x;
    const int b = blockIdx.x;
    if (tid < 32) {
        int r = detect64(ei);
        if (tid == 0) s_is64 = r;
    }
    __syncthreads();
    const int is64 = s_is64;

    const int ebeg = b * EDGE_CHUNK;
    const int eend = min(N_EDGES, ebeg + EDGE_CHUNK);

    // ---- Phase A: histogram of dst + per-edge rank (4 edges/thread/iter) ----
    for (int e0 = ebeg + tid * 4; e0 < eend; e0 += 256 * 4) {
        int d0, d1, d2, d3;
        if (is64) {
            const longlong2* p = (const longlong2*)((const long long*)ei + N_EDGES + e0);
            longlong2 a = __ldg(p);
            longlong2 bb = __ldg(p + 1);
            d0 = (int)a.x; d1 = (int)a.y; d2 = (int)bb.x; d3 = (int)bb.y;
        } else {
            const int* p32 = (const int*)ei;
            int4 v = __ldg((const int4*)(p32 + N_EDGES) + (e0 >> 2));
            d0 = v.x; d1 = v.y; d2 = v.z; d3 = v.w;
        }
        int4 r;
        r.x = atomicAdd(&g_hist[d0], 1);
        r.y = atomicAdd(&g_hist[d1], 1);
        r.z = atomicAdd(&g_hist[d2], 1);
        r.w = atomicAdd(&g_hist[d3], 1);
        *(int4*)(g_rank + e0) = r;
    }
    grid_bar(SORT_BLOCKS);

    // ---- Phase B: exclusive scan hist -> off --------------------------------
    const int nstart = b * NODE_CHUNK;
    const int nend = min(N_NODES, nstart + NODE_CHUNK);
    const int n0 = nstart + tid * 3;
    int v0 = (n0 + 0 < nend) ? g_hist[n0 + 0] : 0;
    int v1 = (n0 + 1 < nend) ? g_hist[n0 + 1] : 0;
    int v2 = (n0 + 2 < nend) ? g_hist[n0 + 2] : 0;
    int s0 = v0, s1 = s0 + v1, s2 = s1 + v2;

    const int lane = tid & 31, w = tid >> 5;
    int inc = s2;
    #pragma unroll
    for (int off = 1; off < 32; off <<= 1) {
        int n_ = __shfl_up_sync(0xFFFFFFFFu, inc, off);
        if (lane >= off) inc += n_;
    }
    if (lane == 31) warp_sums[w] = inc;
    __syncthreads();
    if (tid < 8) {
        int ws = warp_sums[tid];
        #pragma unroll
        for (int off = 1; off < 8; off <<= 1) {
            int n_ = __shfl_up_sync(0xFFu, ws, off);
            if ((int)tid >= off) ws += n_;
        }
        warp_sums[tid] = ws;
    }
    __syncthreads();
    const int warp_prefix = (w > 0) ? warp_sums[w - 1] : 0;
    const int te = warp_prefix + inc - s2;      // thread-exclusive within block
    if (tid == 0) {
        g_bsum[b] = warp_sums[7];               // block total
        s_base = 0;
    }
    grid_bar(2 * SORT_BLOCKS);

    if (tid < b) atomicAdd(&s_base, g_bsum[tid]);
    __syncthreads();
    const int base = s_base + te;
    if (n0 + 0 < nend) g_off[n0 + 0] = base;
    if (n0 + 1 < nend) g_off[n0 + 1] = base + s0;
    if (n0 + 2 < nend) g_off[n0 + 2] = base + s1;
    if (b == SORT_BLOCKS - 1 && tid == 0) g_off[N_NODES] = N_EDGES;
    grid_bar(3 * SORT_BLOCKS);

    // ---- Phase C: placement (atomic-free: pos = off[dst] + rank) ------------
    for (int e0 = ebeg + tid * 4; e0 < eend; e0 += 256 * 4) {
        int s0_, s1_, s2_, s3_, d0, d1, d2, d3;
        if (is64) {
            const longlong2* ps = (const longlong2*)((const long long*)ei + e0);
            const longlong2* pd = (const longlong2*)((const long long*)ei + N_EDGES + e0);
            longlong2 sa = __ldg(ps), sb = __ldg(ps + 1);
            longlong2 da = __ldg(pd), db = __ldg(pd + 1);
            s0_ = (int)sa.x; s1_ = (int)sa.y; s2_ = (int)sb.x; s3_ = (int)sb.y;
            d0 = (int)da.x; d1 = (int)da.y; d2 = (int)db.x; d3 = (int)db.y;
        } else {
            const int* p32 = (const int*)ei;
            int4 sv = __ldg((const int4*)p32 + (e0 >> 2));
            int4 dv = __ldg((const int4*)(p32 + N_EDGES) + (e0 >> 2));
            s0_ = sv.x; s1_ = sv.y; s2_ = sv.z; s3_ = sv.w;
            d0 = dv.x; d1 = dv.y; d2 = dv.z; d3 = dv.w;
        }
        int4 r = __ldg((const int4*)(g_rank + e0));
        g_srcsorted[__ldg(&g_off[d0]) + r.x] = s0_;
        g_srcsorted[__ldg(&g_off[d1]) + r.y] = s1_;
        g_srcsorted[__ldg(&g_off[d2]) + r.z] = s2_;
        g_srcsorted[__ldg(&g_off[d3]) + r.w] = s3_;
    }
}

// ---------------------------------------------------------------------------
// Pre-split weights into bf16 hi/lo, fused B = [Wl ; Wr] per layer.
__global__ __launch_bounds__(256) void prep_w_kernel(
    const float* __restrict__ W1l, const float* __restrict__ W1r,
    const float* __restrict__ W2l, const float* __restrict__ W2r)
{
    int i = blockIdx.x * 256 + threadIdx.x;    // 0 .. 16383
    if (i >= 2 * 128 * 64) return;
    int layer = i >> 13;
    int rem = i & 8191;
    int n = rem >> 6;
    int k = rem & 63;
    const float* W = layer ? (n < 64 ? W2l : W2r) : (n < 64 ? W1l : W1r);
    float v = __ldg(&W[(n & 63) * 64 + k]);
    __nv_bfloat16 h = __float2bfloat16(v);
    __nv_bfloat16 l = __float2bfloat16(v - __bfloat162float(h));
    g_Bh[layer][rem] = h;
    g_Bl[layer][rem] = l;
}

// ---------------------------------------------------------------------------
// mma.sync m16n8k16 bf16 -> f32
__device__ __forceinline__ void mma16816(float* c,
                                         uint32_t a0, uint32_t a1, uint32_t a2, uint32_t a3,
                                         uint32_t b0, uint32_t b1) {
    asm volatile(
        "mma.sync.aligned.m16n8k16.row.col.f32.bf16.bf16.f32 "
        "{%0,%1,%2,%3}, {%4,%5,%6,%7}, {%8,%9}, {%0,%1,%2,%3};"
        : "+f"(c[0]), "+f"(c[1]), "+f"(c[2]), "+f"(c[3])
        : "r"(a0), "r"(a1), "r"(a2), "r"(a3), "r"(b0), "r"(b1));
}

// ---------------------------------------------------------------------------
// Tensor-core transform: per CTA 128 nodes (M) x 128 outs (N = Y|R), K=64.
// 3-term bf16 split: D = Xh*Wh + Xh*Wl + Xl*Wh, fp32 register accumulators.
// Y and R both written as fp16 (half2 pairs); R gets +bias (in fp32) first.
__global__ __launch_bounds__(256)
void transform_mma_kernel(const float4* __restrict__ X,
                          const float* __restrict__ b,
                          int layer, int use_h)
{
    extern __shared__ __nv_bfloat16 sm[];
    __nv_bfloat16* Ah = sm;
    __nv_bfloat16* Al = sm + 128 * PITCH;
    __nv_bfloat16* Bh = sm + 2 * 128 * PITCH;
    __nv_bfloat16* Bl = sm + 3 * 128 * PITCH;

    const int tid = threadIdx.x;
    const int node0 = blockIdx.x * 128;
    const float4* Xv = use_h ? (const float4*)g_h4 : X;

    // Load + split X tile (128 rows x 16 float4 chunks)
    #pragma unroll
    for (int i = tid; i < 2048; i += 256) {
        int n = i >> 4, c = i & 15;
        int gn = node0 + n;
        float4 v = make_float4(0.f, 0.f, 0.f, 0.f);
        if (gn < N_NODES) v = __ldg(Xv + (size_t)gn * 16 + c);
        __nv_bfloat16 hx = __float2bfloat16(v.x), hy = __float2bfloat16(v.y);
        __nv_bfloat16 hz = __float2bfloat16(v.z), hw = __float2bfloat16(v.w);
        __nv_bfloat162 h01, h23, l01, l23;
        h01.x = hx; h01.y = hy; h23.x = hz; h23.y = hw;
        l01.x = __float2bfloat16(v.x - __bfloat162float(hx));
        l01.y = __float2bfloat16(v.y - __bfloat162float(hy));
        l23.x = __float2bfloat16(v.z - __bfloat162float(hz));
        l23.y = __float2bfloat16(v.w - __bfloat162float(hw));
        int base = n * PITCH + c * 4;
        *(__nv_bfloat162*)(Ah + base)     = h01;
        *(__nv_bfloat162*)(Ah + base + 2) = h23;
        *(__nv_bfloat162*)(Al + base)     = l01;
        *(__nv_bfloat162*)(Al + base + 2) = l23;
    }

    // Copy pre-split weights into pitched smem
    {
        const uint32_t* bhp = (const uint32_t*)g_Bh[layer];
        const uint32_t* blp = (const uint32_t*)g_Bl[layer];
        #pragma unroll
        for (int i = tid; i < 4096; i += 256) {
            int n = i >> 5, kp = (i & 31) * 2;
            *(uint32_t*)(Bh + n * PITCH + kp) = __ldg(bhp + i);
            *(uint32_t*)(Bl + n * PITCH + kp) = __ldg(blp + i);
        }
    }
    __syncthreads();

    const int w = tid >> 5, lane = tid & 31;
    const int g = lane >> 2, t = lane & 3;

    float acc[16][4];
    #pragma unroll
    for (int nt = 0; nt < 16; nt++)
        #pragma unroll
        for (int j = 0; j < 4; j++) acc[nt][j] = 0.f;

    const __nv_bfloat16* Aterm[3] = {Ah, Ah, Al};
    const __nv_bfloat16* Bterm[3] = {Bh, Bl, Bh};

    #pragma unroll
    for (int term = 0; term < 3; term++) {
        const __nv_bfloat16* A_ = Aterm[term];
        const __nv_bfloat16* B_ = Bterm[term];
        #pragma unroll
        for (int kk = 0; kk < 4; kk++) {
            const __nv_bfloat16* ar = A_ + (w * 16 + g) * PITCH + kk * 16 + t * 2;
            uint32_t a0 = *(const uint32_t*)ar;
            uint32_t a1 = *(const uint32_t*)(ar + 8 * PITCH);
            uint32_t a2 = *(const uint32_t*)(ar + 8);
            uint32_t a3 = *(const uint32_t*)(ar + 8 * PITCH + 8);
            #pragma unroll
            for (int nt = 0; nt < 16; nt++) {
                const __nv_bfloat16* br = B_ + (nt * 8 + g) * PITCH + kk * 16 + t * 2;
                uint32_t b0 = *(const uint32_t*)br;
                uint32_t b1 = *(const uint32_t*)(br + 8);
                mma16816(acc[nt], a0, a1, a2, a3, b0, b1);
            }
        }
    }

    // Epilogue: c0,c1 -> (row g, cols t*2..+1); c2,c3 -> (row g+8)
    const int row0 = node0 + w * 16 + g;
    const int row1 = row0 + 8;
    uint32_t* Yh = (uint32_t*)g_y4u;      // half2 slots, 32 per node
    uint32_t* Rh = (uint32_t*)g_r4u;      // half2 slots, 32 per node
    #pragma unroll
    for (int nt = 0; nt < 16; nt++) {
        int col = nt * 8 + t * 2;
        if (nt < 8) {
            int hslot = col >> 1;         // = nt*4 + t
            __half2 h01 = __floats2half2_rn(acc[nt][0], acc[nt][1]);
            __half2 h23 = __floats2half2_rn(acc[nt][2], acc[nt][3]);
            if (row0 < N_NODES) Yh[(size_t)row0 * 32 + hslot] = *(uint32_t*)&h01;
            if (row1 < N_NODES) Yh[(size_t)row1 * 32 + hslot] = *(uint32_t*)&h23;
        } else {
            int rc = col - 64;
            int hslot = rc >> 1;
            float2 bb = __ldg((const float2*)(b + rc));
            __half2 h01 = __floats2half2_rn(acc[nt][0] + bb.x, acc[nt][1] + bb.y);
            __half2 h23 = __floats2half2_rn(acc[nt][2] + bb.x, acc[nt][3] + bb.y);
            if (row0 < N_NODES) Rh[(size_t)row0 * 32 + hslot] = *(uint32_t*)&h01;
            if (row1 < N_NODES) Rh[(size_t)row1 * 32 + hslot] = *(uint32_t*)&h23;
        }
    }
}

// ---------------------------------------------------------------------------
// Gather-aggregate + combine. 8 lanes per node, 8 columns (one uint4 of fp16).
// Layer 1 re-zeroes hist/bar_count for the next graph replay.
__global__ __launch_bounds__(256) void gather_combine_kernel(
    float4* __restrict__ Out, int layer)
{
    int idx = blockIdx.x * 256 + threadIdx.x;   // exactly N_NODES*8
    int n = idx >> 3;
    int c = idx & 7;
    int beg = __ldg(&g_off[n]);
    int end = __ldg(&g_off[n + 1]);

    float a0 = 0.f, a1 = 0.f, a2 = 0.f, a3 = 0.f;
    float a4 = 0.f, a5 = 0.f, a6 = 0.f, a7 = 0.f;
    #pragma unroll 4
    for (int e = beg; e < end; e++) {
        int s = __ldg(&g_srcsorted[e]);
        uint4 u = __ldg(&g_y4u[s * 8 + c]);
        float2 f0 = __half22float2(*(__half2*)&u.x);
        float2 f1 = __half22float2(*(__half2*)&u.y);
        float2 f2 = __half22float2(*(__half2*)&u.z);
        float2 f3 = __half22float2(*(__half2*)&u.w);
        a0 += f0.x; a1 += f0.y; a2 += f1.x; a3 += f1.y;
        a4 += f2.x; a5 += f2.y; a6 += f3.x; a7 += f3.y;
    }
    float invd = 1.f / fmaxf((float)(end - beg), 1.f);
    uint4 ru = __ldg(&g_r4u[n * 8 + c]);
    float2 r0 = __half22float2(*(__half2*)&ru.x);
    float2 r1 = __half22float2(*(__half2*)&ru.y);
    float2 r2 = __half22float2(*(__half2*)&ru.z);
    float2 r3 = __half22float2(*(__half2*)&ru.w);
    float4 o0 = make_float4(a0 * invd + r0.x, a1 * invd + r0.y,
                            a2 * invd + r1.x, a3 * invd + r1.y);
    float4 o1 = make_float4(a4 * invd + r2.x, a5 * invd + r2.y,
                            a6 * invd + r3.x, a7 * invd + r3.y);
    if (layer == 1) {
        o0.x = fmaxf(o0.x, 0.f); o0.y = fmaxf(o0.y, 0.f);
        o0.z = fmaxf(o0.z, 0.f); o0.w = fmaxf(o0.w, 0.f);
        o1.x = fmaxf(o1.x, 0.f); o1.y = fmaxf(o1.y, 0.f);
        o1.z = fmaxf(o1.z, 0.f); o1.w = fmaxf(o1.w, 0.f);
        g_h4[n * 16 + c * 2]     = o0;
        g_h4[n * 16 + c * 2 + 1] = o1;
        if (c == 0) g_hist[n] = 0;                        // next-replay reset
        if (blockIdx.x == 0 && threadIdx.x == 0) g_bar_count = 0;
    } else {
        Out[n * 16 + c * 2]     = o0;
        Out[n * 16 + c * 2 + 1] = o1;
    }
}

// ---------------------------------------------------------------------------
extern "C" void kernel_launch(void* const* d_in, const int* in_sizes, int n_in,
                              void* d_out, int out_size) {
    const float* x   = (const float*)d_in[0];
    const void*  ei  = d_in[1];
    const float* W1l = (const float*)d_in[2];
    const float* b1  = (const float*)d_in[3];
    const float* W1r = (const float*)d_in[4];
    const float* W2l = (const float*)d_in[5];
    const float* b2  = (const float*)d_in[6];
    const float* W2r = (const float*)d_in[7];

    const int SMEM_BYTES = 4 * 128 * PITCH * 2;   // 73728
    static cudaStream_t s2 = nullptr;
    static cudaEvent_t evFork = nullptr, evJoin = nullptr;
    if (!s2) {
        cudaStreamCreateWithFlags(&s2, cudaStreamNonBlocking);
        cudaEventCreateWithFlags(&evFork, cudaEventDisableTiming);
        cudaEventCreateWithFlags(&evJoin, cudaEventDisableTiming);
        cudaFuncSetAttribute(transform_mma_kernel,
                             cudaFuncAttributeMaxDynamicSharedMemorySize, SMEM_BYTES);
    }

    const int GG = (N_NODES * 8) / 256;     // 3125 (exact)

    // Fork: weight prep + layer-1 transform concurrent with fused edge sort.
    cudaEventRecord(evFork, 0);
    cudaStreamWaitEvent(s2, evFork, 0);
    prep_w_kernel<<<64, 256, 0, s2>>>(W1l, W1r, W2l, W2r);
    transform_mma_kernel<<<TC_BLOCKS, 256, SMEM_BYTES, s2>>>((const float4*)x, b1, 0, 0);
    cudaEventRecord(evJoin, s2);

    // Fused sort (stream 0); hist/bar_count zeroed by prior gather L1
    sort_kernel<<<SORT_BLOCKS, 256>>>(ei);

    // Join, then aggregate
    cudaStreamWaitEvent(0, evJoin, 0);
    gather_combine_kernel<<<GG, 256>>>(nullptr, 1);

    // Layer 2
    transform_mma_kernel<<<TC_BLOCKS, 256, SMEM_BYTES>>>(nullptr, b2, 1, 1);
    gather_combine_kernel<<<GG, 256>>>((float4*)d_out, 2);
}

// round 15
// speedup vs baseline: 1.0720x; 1.0720x over previous
#include <cuda_runtime.h>
#include <cuda_bf16.h>
#include <cuda_fp16.h>
#include <cstdint>

#define N_NODES 100000
#define N_EDGES 1280000
#define D 64
#define NB_SCAN 98            // ceil(100000 / 1024)
#define TC_BLOCKS 782         // ceil(100000 / 128)
#define PITCH 72              // smem row pitch in bf16 (144B) -> conflict-free frags

// ---------------------------------------------------------------------------
// Scratch (__device__ globals; zero-initialized at module load)
__device__ uint4  g_y4u[N_NODES * 8];   // x @ W_l^T in fp16 (8 halves per uint4)
__device__ uint4  g_r4u[N_NODES * 8];   // x @ W_r^T + b in fp16 (8 halves/uint4)
__device__ float4 g_h4[N_NODES * 16];   // layer-1 output (fp32)
__device__ int    g_hist[N_NODES];      // re-zeroed by gather L1
__device__ int    g_rank[N_EDGES];      // per-edge slot within its dst segment
__device__ int    g_scanpub[NB_SCAN];   // re-zeroed by gather L1
__device__ int    g_off[N_NODES + 1];
__device__ __align__(16) int g_srcsorted[N_EDGES];
// Pre-split weights: rows n: n<64 -> Wl[n], n>=64 -> Wr[n-64]; [layer][n*64+k]
__device__ __nv_bfloat16 g_Bh[2][128 * 64];
__device__ __nv_bfloat16 g_Bl[2][128 * 64];

// ---------------------------------------------------------------------------
// Warp-uniform edge dtype probe: int64 interp valid iff 32 samples in range.
__device__ __forceinline__ int detect64(const void* ei) {
    const long long* p = (const long long*)ei;
    int lane = threadIdx.x & 31;
    long long v = __ldg(&p[lane * 317]);
    return __all_sync(0xFFFFFFFFu, v >= 0 && v < N_NODES);
}

// ---------------------------------------------------------------------------
// Histogram of dst + rank capture (4 edges/thread). Grid: 1250x256 (exact).
__global__ __launch_bounds__(256) void hist_kernel(const void* __restrict__ ei) {
    const int is64 = detect64(ei);
    const int e0 = (blockIdx.x * 256 + threadIdx.x) * 4;
    int d0, d1, d2, d3;
    if (is64) {
        const longlong2* p = (const longlong2*)((const long long*)ei + N_EDGES + e0);
        longlong2 a = __ldg(p);
        longlong2 b = __ldg(p + 1);
        d0 = (int)a.x; d1 = (int)a.y; d2 = (int)b.x; d3 = (int)b.y;
    } else {
        const int* p32 = (const int*)ei;
        int4 v = __ldg((const int4*)(p32 + N_EDGES) + (e0 >> 2));
        d0 = v.x; d1 = v.y; d2 = v.z; d3 = v.w;
    }
    int4 r;
    r.x = atomicAdd(&g_hist[d0], 1);
    r.y = atomicAdd(&g_hist[d1], 1);
    r.z = atomicAdd(&g_hist[d2], 1);
    r.w = atomicAdd(&g_hist[d3], 1);
    *(int4*)(g_rank + e0) = r;
}

// ---------------------------------------------------------------------------
// Single-kernel exclusive scan (98 blocks): publish block totals, lookback sum.
// All 98 blocks co-resident (<< 148 SMs) so spinning cannot deadlock.
__global__ __launch_bounds__(256) void scan_kernel() {
    __shared__ int warp_sums[8];
    __shared__ int base_sh;
    const int b = blockIdx.x, t = threadIdx.x;
    const int base = b * 1024 + t * 4;
    int v0 = (base + 0 < N_NODES) ? g_hist[base + 0] : 0;
    int v1 = (base + 1 < N_NODES) ? g_hist[base + 1] : 0;
    int v2 = (base + 2 < N_NODES) ? g_hist[base + 2] : 0;
    int v3 = (base + 3 < N_NODES) ? g_hist[base + 3] : 0;
    int s0 = v0, s1 = s0 + v1, s2 = s1 + v2, s3 = s2 + v3;
    const int lane = t & 31, w = t >> 5;
    int inc = s3;
    #pragma unroll
    for (int off = 1; off < 32; off <<= 1) {
        int n_ = __shfl_up_sync(0xFFFFFFFFu, inc, off);
        if (lane >= off) inc += n_;
    }
    if (lane == 31) warp_sums[w] = inc;
    __syncthreads();
    if (t < 8) {
        int ws = warp_sums[t];
        #pragma unroll
        for (int off = 1; off < 8; off <<= 1) {
            int n_ = __shfl_up_sync(0xFFu, ws, off);
            if ((int)t >= off) ws += n_;
        }
        warp_sums[t] = ws;
    }
    __syncthreads();
    if (t == 0) {
        base_sh = 0;
        atomicExch(&g_scanpub[b], warp_sums[7] + 1);
    }
    __syncthreads();
    for (int i = t; i < b; i += 256) {
        int v;
        do { v = atomicAdd(&g_scanpub[i], 0); } while (v == 0);
        atomicAdd(&base_sh, v - 1);
    }
    __syncthreads();
    const int blk_base = base_sh;
    int warp_prefix = (w > 0) ? warp_sums[w - 1] : 0;
    int te = blk_base + warp_prefix + inc - s3;
    if (base + 0 < N_NODES) g_off[base + 0] = te;
    if (base + 1 < N_NODES) g_off[base + 1] = te + s0;
    if (base + 2 < N_NODES) g_off[base + 2] = te + s1;
    if (base + 3 < N_NODES) g_off[base + 3] = te + s2;
    if (b == NB_SCAN - 1 && t == 0) g_off[N_NODES] = N_EDGES;
}

// ---------------------------------------------------------------------------
// Placement: atomic-free, pos = off[dst] + rank. 4 edges/thread. 1250 blocks.
__global__ __launch_bounds__(256) void place_kernel(const void* __restrict__ ei) {
    const int is64 = detect64(ei);
    const int e0 = (blockIdx.x * 256 + threadIdx.x) * 4;
    int s0, s1, s2, s3, d0, d1, d2, d3;
    if (is64) {
        const longlong2* ps = (const longlong2*)((const long long*)ei + e0);
        const longlong2* pd = (const longlong2*)((const long long*)ei + N_EDGES + e0);
        longlong2 sa = __ldg(ps), sb = __ldg(ps + 1);
        longlong2 da = __ldg(pd), db = __ldg(pd + 1);
        s0 = (int)sa.x; s1 = (int)sa.y; s2 = (int)sb.x; s3 = (int)sb.y;
        d0 = (int)da.x; d1 = (int)da.y; d2 = (int)db.x; d3 = (int)db.y;
    } else {
        const int* p32 = (const int*)ei;
        int4 sv = __ldg((const int4*)p32 + (e0 >> 2));
        int4 dv = __ldg((const int4*)(p32 + N_EDGES) + (e0 >> 2));
        s0 = sv.x; s1 = sv.y; s2 = sv.z; s3 = sv.w;
        d0 = dv.x; d1 = dv.y; d2 = dv.z; d3 = dv.w;
    }
    int4 r = __ldg((const int4*)(g_rank + e0));
    g_srcsorted[__ldg(&g_off[d0]) + r.x] = s0;
    g_srcsorted[__ldg(&g_off[d1]) + r.y] = s1;
    g_srcsorted[__ldg(&g_off[d2]) + r.z] = s2;
    g_srcsorted[__ldg(&g_off[d3]) + r.w] = s3;
}

// ---------------------------------------------------------------------------
// Pre-split weights into bf16 hi/lo, fused B = [Wl ; Wr] per layer.
__global__ __launch_bounds__(256) void prep_w_kernel(
    const float* __restrict__ W1l, const float* __restrict__ W1r,
    const float* __restrict__ W2l, const float* __restrict__ W2r)
{
    int i = blockIdx.x * 256 + threadIdx.x;    // 0 .. 16383
    if (i >= 2 * 128 * 64) return;
    int layer = i >> 13;
    int rem = i & 8191;
    int n = rem >> 6;
    int k = rem & 63;
    const float* W = layer ? (n < 64 ? W2l : W2r) : (n < 64 ? W1l : W1r);
    float v = __ldg(&W[(n & 63) * 64 + k]);
    __nv_bfloat16 h = __float2bfloat16(v);
    __nv_bfloat16 l = __float2bfloat16(v - __bfloat162float(h));
    g_Bh[layer][rem] = h;
    g_Bl[layer][rem] = l;
}

// ---------------------------------------------------------------------------
// mma.sync m16n8k16 bf16 -> f32
__device__ __forceinline__ void mma16816(float* c,
                                         uint32_t a0, uint32_t a1, uint32_t a2, uint32_t a3,
                                         uint32_t b0, uint32_t b1) {
    asm volatile(
        "mma.sync.aligned.m16n8k16.row.col.f32.bf16.bf16.f32 "
        "{%0,%1,%2,%3}, {%4,%5,%6,%7}, {%8,%9}, {%0,%1,%2,%3};"
        : "+f"(c[0]), "+f"(c[1]), "+f"(c[2]), "+f"(c[3])
        : "r"(a0), "r"(a1), "r"(a2), "r"(a3), "r"(b0), "r"(b1));
}

// ---------------------------------------------------------------------------
// Tensor-core transform: per CTA 128 nodes (M) x 128 outs (N = Y|R), K=64.
// 3-term bf16 split: D = Xh*Wh + Xh*Wl + Xl*Wh, fp32 register accumulators.
// Y and R both written as fp16 (half2 pairs); R gets +bias (in fp32) first.
__global__ __launch_bounds__(256)
void transform_mma_kernel(const float4* __restrict__ X,
                          const float* __restrict__ b,
                          int layer, int use_h)
{
    extern __shared__ __nv_bfloat16 sm[];
    __nv_bfloat16* Ah = sm;
    __nv_bfloat16* Al = sm + 128 * PITCH;
    __nv_bfloat16* Bh = sm + 2 * 128 * PITCH;
    __nv_bfloat16* Bl = sm + 3 * 128 * PITCH;

    const int tid = threadIdx.x;
    const int node0 = blockIdx.x * 128;
    const float4* Xv = use_h ? (const float4*)g_h4 : X;

    // Load + split X tile (128 rows x 16 float4 chunks)
    #pragma unroll
    for (int i = tid; i < 2048; i += 256) {
        int n = i >> 4, c = i & 15;
        int gn = node0 + n;
        float4 v = make_float4(0.f, 0.f, 0.f, 0.f);
        if (gn < N_NODES) v = __ldg(Xv + (size_t)gn * 16 + c);
        __nv_bfloat16 hx = __float2bfloat16(v.x), hy = __float2bfloat16(v.y);
        __nv_bfloat16 hz = __float2bfloat16(v.z), hw = __float2bfloat16(v.w);
        __nv_bfloat162 h01, h23, l01, l23;
        h01.x = hx; h01.y = hy; h23.x = hz; h23.y = hw;
        l01.x = __float2bfloat16(v.x - __bfloat162float(hx));
        l01.y = __float2bfloat16(v.y - __bfloat162float(hy));
        l23.x = __float2bfloat16(v.z - __bfloat162float(hz));
        l23.y = __float2bfloat16(v.w - __bfloat162float(hw));
        int base = n * PITCH + c * 4;
        *(__nv_bfloat162*)(Ah + base)     = h01;
        *(__nv_bfloat162*)(Ah + base + 2) = h23;
        *(__nv_bfloat162*)(Al + base)     = l01;
        *(__nv_bfloat162*)(Al + base + 2) = l23;
    }

    // Copy pre-split weights into pitched smem
    {
        const uint32_t* bhp = (const uint32_t*)g_Bh[layer];
        const uint32_t* blp = (const uint32_t*)g_Bl[layer];
        #pragma unroll
        for (int i = tid; i < 4096; i += 256) {
            int n = i >> 5, kp = (i & 31) * 2;
            *(uint32_t*)(Bh + n * PITCH + kp) = __ldg(bhp + i);
            *(uint32_t*)(Bl + n * PITCH + kp) = __ldg(blp + i);
        }
    }
    __syncthreads();

    const int w = tid >> 5, lane = tid & 31;
    const int g = lane >> 2, t = lane & 3;

    float acc[16][4];
    #pragma unroll
    for (int nt = 0; nt < 16; nt++)
        #pragma unroll
        for (int j = 0; j < 4; j++) acc[nt][j] = 0.f;

    const __nv_bfloat16* Aterm[3] = {Ah, Ah, Al};
    const __nv_bfloat16* Bterm[3] = {Bh, Bl, Bh};

    #pragma unroll
    for (int term = 0; term < 3; term++) {
        const __nv_bfloat16* A_ = Aterm[term];
        const __nv_bfloat16* B_ = Bterm[term];
        #pragma unroll
        for (int kk = 0; kk < 4; kk++) {
            const __nv_bfloat16* ar = A_ + (w * 16 + g) * PITCH + kk * 16 + t * 2;
            uint32_t a0 = *(const uint32_t*)ar;
            uint32_t a1 = *(const uint32_t*)(ar + 8 * PITCH);
            uint32_t a2 = *(const uint32_t*)(ar + 8);
            uint32_t a3 = *(const uint32_t*)(ar + 8 * PITCH + 8);
            #pragma unroll
            for (int nt = 0; nt < 16; nt++) {
                const __nv_bfloat16* br = B_ + (nt * 8 + g) * PITCH + kk * 16 + t * 2;
                uint32_t b0 = *(const uint32_t*)br;
                uint32_t b1 = *(const uint32_t*)(br + 8);
                mma16816(acc[nt], a0, a1, a2, a3, b0, b1);
            }
        }
    }

    // Epilogue: c0,c1 -> (row g, cols t*2..+1); c2,c3 -> (row g+8)
    const int row0 = node0 + w * 16 + g;
    const int row1 = row0 + 8;
    uint32_t* Yh = (uint32_t*)g_y4u;      // half2 slots, 32 per node
    uint32_t* Rh = (uint32_t*)g_r4u;      // half2 slots, 32 per node
    #pragma unroll
    for (int nt = 0; nt < 16; nt++) {
        int col = nt * 8 + t * 2;
        if (nt < 8) {
            int hslot = col >> 1;         // = nt*4 + t
            __half2 h01 = __floats2half2_rn(acc[nt][0], acc[nt][1]);
            __half2 h23 = __floats2half2_rn(acc[nt][2], acc[nt][3]);
            if (row0 < N_NODES) Yh[(size_t)row0 * 32 + hslot] = *(uint32_t*)&h01;
            if (row1 < N_NODES) Yh[(size_t)row1 * 32 + hslot] = *(uint32_t*)&h23;
        } else {
            int rc = col - 64;
            int hslot = rc >> 1;
            float2 bb = __ldg((const float2*)(b + rc));
            __half2 h01 = __floats2half2_rn(acc[nt][0] + bb.x, acc[nt][1] + bb.y);
            __half2 h23 = __floats2half2_rn(acc[nt][2] + bb.x, acc[nt][3] + bb.y);
            if (row0 < N_NODES) Rh[(size_t)row0 * 32 + hslot] = *(uint32_t*)&h01;
            if (row1 < N_NODES) Rh[(size_t)row1 * 32 + hslot] = *(uint32_t*)&h23;
        }
    }
}

// ---------------------------------------------------------------------------
// Gather-aggregate + combine. 8 lanes per node, 8 columns (one uint4 of fp16).
// Edge PAIRS are pre-summed in fp16 (HADD2) before fp32 accumulation: per 2
// edges -> 1 int2 index load + 2 row loads + 4 HADD2 + 8 cvt + 8 FADD.
// Layer 1 re-zeroes hist/scanpub for the next graph replay.
__global__ __launch_bounds__(256) void gather_combine_kernel(
    float4* __restrict__ Out, int layer)
{
    int idx = blockIdx.x * 256 + threadIdx.x;   // exactly N_NODES*8
    int n = idx >> 3;
    int c = idx & 7;
    int beg = __ldg(&g_off[n]);
    int end = __ldg(&g_off[n + 1]);

    float a0 = 0.f, a1 = 0.f, a2 = 0.f, a3 = 0.f;
    float a4 = 0.f, a5 = 0.f, a6 = 0.f, a7 = 0.f;

    int e = beg;
    // odd leading edge (keeps int2 loads 8B-aligned)
    if ((e & 1) && e < end) {
        int s = __ldg(&g_srcsorted[e]);
        uint4 u = __ldg(&g_y4u[s * 8 + c]);
        float2 f0 = __half22float2(*(__half2*)&u.x);
        float2 f1 = __half22float2(*(__half2*)&u.y);
        float2 f2 = __half22float2(*(__half2*)&u.z);
        float2 f3 = __half22float2(*(__half2*)&u.w);
        a0 += f0.x; a1 += f0.y; a2 += f1.x; a3 += f1.y;
        a4 += f2.x; a5 += f2.y; a6 += f3.x; a7 += f3.y;
        e++;
    }
    #pragma unroll 2
    for (; e + 2 <= end; e += 2) {
        int2 ss = __ldg((const int2*)(g_srcsorted + e));
        uint4 u0 = __ldg(&g_y4u[ss.x * 8 + c]);
        uint4 u1 = __ldg(&g_y4u[ss.y * 8 + c]);
        __half2 q0 = __hadd2(*(__half2*)&u0.x, *(__half2*)&u1.x);
        __half2 q1 = __hadd2(*(__half2*)&u0.y, *(__half2*)&u1.y);
        __half2 q2 = __hadd2(*(__half2*)&u0.z, *(__half2*)&u1.z);
        __half2 q3 = __hadd2(*(__half2*)&u0.w, *(__half2*)&u1.w);
        float2 f0 = __half22float2(q0);
        float2 f1 = __half22float2(q1);
        float2 f2 = __half22float2(q2);
        float2 f3 = __half22float2(q3);
        a0 += f0.x; a1 += f0.y; a2 += f1.x; a3 += f1.y;
        a4 += f2.x; a5 += f2.y; a6 += f3.x; a7 += f3.y;
    }
    if (e < end) {
        int s = __ldg(&g_srcsorted[e]);
        uint4 u = __ldg(&g_y4u[s * 8 + c]);
        float2 f0 = __half22float2(*(__half2*)&u.x);
        float2 f1 = __half22float2(*(__half2*)&u.y);
        float2 f2 = __half22float2(*(__half2*)&u.z);
        float2 f3 = __half22float2(*(__half2*)&u.w);
        a0 += f0.x; a1 += f0.y; a2 += f1.x; a3 += f1.y;
        a4 += f2.x; a5 += f2.y; a6 += f3.x; a7 += f3.y;
    }

    float invd = 1.f / fmaxf((float)(end - beg), 1.f);
    uint4 ru = __ldg(&g_r4u[n * 8 + c]);
    float2 r0 = __half22float2(*(__half2*)&ru.x);
    float2 r1 = __half22float2(*(__half2*)&ru.y);
    float2 r2 = __half22float2(*(__half2*)&ru.z);
    float2 r3 = __half22float2(*(__half2*)&ru.w);
    float4 o0 = make_float4(a0 * invd + r0.x, a1 * invd + r0.y,
                            a2 * invd + r1.x, a3 * invd + r1.y);
    float4 o1 = make_float4(a4 * invd + r2.x, a5 * invd + r2.y,
                            a6 * invd + r3.x, a7 * invd + r3.y);
    if (layer == 1) {
        o0.x = fmaxf(o0.x, 0.f); o0.y = fmaxf(o0.y, 0.f);
        o0.z = fmaxf(o0.z, 0.f); o0.w = fmaxf(o0.w, 0.f);
        o1.x = fmaxf(o1.x, 0.f); o1.y = fmaxf(o1.y, 0.f);
        o1.z = fmaxf(o1.z, 0.f); o1.w = fmaxf(o1.w, 0.f);
        g_h4[n * 16 + c * 2]     = o0;
        g_h4[n * 16 + c * 2 + 1] = o1;
        if (c == 0) g_hist[n] = 0;
        if (blockIdx.x == 0 && threadIdx.x < NB_SCAN) g_scanpub[threadIdx.x] = 0;
    } else {
        Out[n * 16 + c * 2]     = o0;
        Out[n * 16 + c * 2 + 1] = o1;
    }
}

// ---------------------------------------------------------------------------
extern "C" void kernel_launch(void* const* d_in, const int* in_sizes, int n_in,
                              void* d_out, int out_size) {
    const float* x   = (const float*)d_in[0];
    const void*  ei  = d_in[1];
    const float* W1l = (const float*)d_in[2];
    const float* b1  = (const float*)d_in[3];
    const float* W1r = (const float*)d_in[4];
    const float* W2l = (const float*)d_in[5];
    const float* b2  = (const float*)d_in[6];
    const float* W2r = (const float*)d_in[7];

    const int SMEM_BYTES = 4 * 128 * PITCH * 2;   // 73728
    static cudaStream_t s2 = nullptr;
    static cudaEvent_t evFork = nullptr, evJoin = nullptr;
    if (!s2) {
        cudaStreamCreateWithFlags(&s2, cudaStreamNonBlocking);
        cudaEventCreateWithFlags(&evFork, cudaEventDisableTiming);
        cudaEventCreateWithFlags(&evJoin, cudaEventDisableTiming);
        cudaFuncSetAttribute(transform_mma_kernel,
                             cudaFuncAttributeMaxDynamicSharedMemorySize, SMEM_BYTES);
    }

    const int GG = (N_NODES * 8) / 256;     // 3125 (exact)

    // Fork: weight prep + layer-1 transform concurrent with edge sort.
    cudaEventRecord(evFork, 0);
    cudaStreamWaitEvent(s2, evFork, 0);
    prep_w_kernel<<<64, 256, 0, s2>>>(W1l, W1r, W2l, W2r);
    transform_mma_kernel<<<TC_BLOCKS, 256, SMEM_BYTES, s2>>>((const float4*)x, b1, 0, 0);
    cudaEventRecord(evJoin, s2);

    // Edge sort pipeline (stream 0); hist/scanpub zeroed by prior gather L1
    hist_kernel<<<N_EDGES / 1024, 256>>>(ei);          // 1250 blocks
    scan_kernel<<<NB_SCAN, 256>>>();
    place_kernel<<<N_EDGES / 1024, 256>>>(ei);         // 1250 blocks, atomic-free

    // Join, then aggregate
    cudaStreamWaitEvent(0, evJoin, 0);
    gather_combine_kernel<<<GG, 256>>>(nullptr, 1);

    // Layer 2
    transform_mma_kernel<<<TC_BLOCKS, 256, SMEM_BYTES>>>(nullptr, b2, 1, 1);
    gather_combine_kernel<<<GG, 256>>>((float4*)d_out, 2);
}

// round 16
// speedup vs baseline: 1.0742x; 1.0021x over previous
#include <cuda_runtime.h>
#include <cuda_bf16.h>
#include <cuda_fp16.h>
#include <cstdint>

#define N_NODES 100000
#define N_EDGES 1280000
#define D 64
#define NB_SCAN 98            // ceil(100000 / 1024)
#define TC_BLOCKS 782         // ceil(100000 / 128)
#define PITCH 72              // smem row pitch in bf16 (144B) -> conflict-free frags

// ---------------------------------------------------------------------------
// Scratch (__device__ globals; zero-initialized at module load)
__device__ uint4  g_y4u[N_NODES * 8];   // x @ W_l^T in fp16 (8 halves per uint4)
__device__ uint4  g_r4u[N_NODES * 8];   // x @ W_r^T + b in fp16 (8 halves/uint4)
__device__ float4 g_h4[N_NODES * 16];   // layer-1 output (fp32)
__device__ int    g_hist[N_NODES];      // re-zeroed by gather L1
__device__ int    g_rank[N_EDGES];      // per-edge slot within its dst segment
__device__ int    g_scanpub[NB_SCAN];   // re-zeroed by gather L1
__device__ int    g_off[N_NODES + 1];
__device__ __align__(16) int g_srcsorted[N_EDGES];
// Pre-split weights: rows n: n<64 -> Wl[n], n>=64 -> Wr[n-64]; [layer][n*64+k]
__device__ __nv_bfloat16 g_Bh[2][128 * 64];
__device__ __nv_bfloat16 g_Bl[2][128 * 64];

// ---------------------------------------------------------------------------
// Warp-uniform edge dtype probe: int64 interp valid iff 32 samples in range.
__device__ __forceinline__ int detect64(const void* ei) {
    const long long* p = (const long long*)ei;
    int lane = threadIdx.x & 31;
    long long v = __ldg(&p[lane * 317]);
    return __all_sync(0xFFFFFFFFu, v >= 0 && v < N_NODES);
}

// ---------------------------------------------------------------------------
// Histogram of dst + rank capture (4 edges/thread). Grid: 1250x256 (exact).
__global__ __launch_bounds__(256) void hist_kernel(const void* __restrict__ ei) {
    const int is64 = detect64(ei);
    const int e0 = (blockIdx.x * 256 + threadIdx.x) * 4;
    int d0, d1, d2, d3;
    if (is64) {
        const longlong2* p = (const longlong2*)((const long long*)ei + N_EDGES + e0);
        longlong2 a = __ldg(p);
        longlong2 b = __ldg(p + 1);
        d0 = (int)a.x; d1 = (int)a.y; d2 = (int)b.x; d3 = (int)b.y;
    } else {
        const int* p32 = (const int*)ei;
        int4 v = __ldg((const int4*)(p32 + N_EDGES) + (e0 >> 2));
        d0 = v.x; d1 = v.y; d2 = v.z; d3 = v.w;
    }
    int4 r;
    r.x = atomicAdd(&g_hist[d0], 1);
    r.y = atomicAdd(&g_hist[d1], 1);
    r.z = atomicAdd(&g_hist[d2], 1);
    r.w = atomicAdd(&g_hist[d3], 1);
    *(int4*)(g_rank + e0) = r;
}

// ---------------------------------------------------------------------------
// Single-kernel exclusive scan (98 blocks): publish block totals, lookback sum.
// All 98 blocks co-resident (<< 148 SMs) so spinning cannot deadlock.
__global__ __launch_bounds__(256) void scan_kernel() {
    __shared__ int warp_sums[8];
    __shared__ int base_sh;
    const int b = blockIdx.x, t = threadIdx.x;
    const int base = b * 1024 + t * 4;
    int v0 = (base + 0 < N_NODES) ? g_hist[base + 0] : 0;
    int v1 = (base + 1 < N_NODES) ? g_hist[base + 1] : 0;
    int v2 = (base + 2 < N_NODES) ? g_hist[base + 2] : 0;
    int v3 = (base + 3 < N_NODES) ? g_hist[base + 3] : 0;
    int s0 = v0, s1 = s0 + v1, s2 = s1 + v2, s3 = s2 + v3;
    const int lane = t & 31, w = t >> 5;
    int inc = s3;
    #pragma unroll
    for (int off = 1; off < 32; off <<= 1) {
        int n_ = __shfl_up_sync(0xFFFFFFFFu, inc, off);
        if (lane >= off) inc += n_;
    }
    if (lane == 31) warp_sums[w] = inc;
    __syncthreads();
    if (t < 8) {
        int ws = warp_sums[t];
        #pragma unroll
        for (int off = 1; off < 8; off <<= 1) {
            int n_ = __shfl_up_sync(0xFFu, ws, off);
            if ((int)t >= off) ws += n_;
        }
        warp_sums[t] = ws;
    }
    __syncthreads();
    if (t == 0) {
        base_sh = 0;
        atomicExch(&g_scanpub[b], warp_sums[7] + 1);
    }
    __syncthreads();
    for (int i = t; i < b; i += 256) {
        int v;
        do { v = atomicAdd(&g_scanpub[i], 0); } while (v == 0);
        atomicAdd(&base_sh, v - 1);
    }
    __syncthreads();
    const int blk_base = base_sh;
    int warp_prefix = (w > 0) ? warp_sums[w - 1] : 0;
    int te = blk_base + warp_prefix + inc - s3;
    if (base + 0 < N_NODES) g_off[base + 0] = te;
    if (base + 1 < N_NODES) g_off[base + 1] = te + s0;
    if (base + 2 < N_NODES) g_off[base + 2] = te + s1;
    if (base + 3 < N_NODES) g_off[base + 3] = te + s2;
    if (b == NB_SCAN - 1 && t == 0) g_off[N_NODES] = N_EDGES;
}

// ---------------------------------------------------------------------------
// Placement: atomic-free, pos = off[dst] + rank. 4 edges/thread. 1250 blocks.
__global__ __launch_bounds__(256) void place_kernel(const void* __restrict__ ei) {
    const int is64 = detect64(ei);
    const int e0 = (blockIdx.x * 256 + threadIdx.x) * 4;
    int s0, s1, s2, s3, d0, d1, d2, d3;
    if (is64) {
        const longlong2* ps = (const longlong2*)((const long long*)ei + e0);
        const longlong2* pd = (const longlong2*)((const long long*)ei + N_EDGES + e0);
        longlong2 sa = __ldg(ps), sb = __ldg(ps + 1);
        longlong2 da = __ldg(pd), db = __ldg(pd + 1);
        s0 = (int)sa.x; s1 = (int)sa.y; s2 = (int)sb.x; s3 = (int)sb.y;
        d0 = (int)da.x; d1 = (int)da.y; d2 = (int)db.x; d3 = (int)db.y;
    } else {
        const int* p32 = (const int*)ei;
        int4 sv = __ldg((const int4*)p32 + (e0 >> 2));
        int4 dv = __ldg((const int4*)(p32 + N_EDGES) + (e0 >> 2));
        s0 = sv.x; s1 = sv.y; s2 = sv.z; s3 = sv.w;
        d0 = dv.x; d1 = dv.y; d2 = dv.z; d3 = dv.w;
    }
    int4 r = __ldg((const int4*)(g_rank + e0));
    g_srcsorted[__ldg(&g_off[d0]) + r.x] = s0;
    g_srcsorted[__ldg(&g_off[d1]) + r.y] = s1;
    g_srcsorted[__ldg(&g_off[d2]) + r.z] = s2;
    g_srcsorted[__ldg(&g_off[d3]) + r.w] = s3;
}

// ---------------------------------------------------------------------------
// Pre-split weights into bf16 hi/lo, fused B = [Wl ; Wr] per layer.
__global__ __launch_bounds__(256) void prep_w_kernel(
    const float* __restrict__ W1l, const float* __restrict__ W1r,
    const float* __restrict__ W2l, const float* __restrict__ W2r)
{
    int i = blockIdx.x * 256 + threadIdx.x;    // 0 .. 16383
    if (i >= 2 * 128 * 64) return;
    int layer = i >> 13;
    int rem = i & 8191;
    int n = rem >> 6;
    int k = rem & 63;
    const float* W = layer ? (n < 64 ? W2l : W2r) : (n < 64 ? W1l : W1r);
    float v = __ldg(&W[(n & 63) * 64 + k]);
    __nv_bfloat16 h = __float2bfloat16(v);
    __nv_bfloat16 l = __float2bfloat16(v - __bfloat162float(h));
    g_Bh[layer][rem] = h;
    g_Bl[layer][rem] = l;
}

// ---------------------------------------------------------------------------
// mma.sync m16n8k16 bf16 -> f32
__device__ __forceinline__ void mma16816(float* c,
                                         uint32_t a0, uint32_t a1, uint32_t a2, uint32_t a3,
                                         uint32_t b0, uint32_t b1) {
    asm volatile(
        "mma.sync.aligned.m16n8k16.row.col.f32.bf16.bf16.f32 "
        "{%0,%1,%2,%3}, {%4,%5,%6,%7}, {%8,%9}, {%0,%1,%2,%3};"
        : "+f"(c[0]), "+f"(c[1]), "+f"(c[2]), "+f"(c[3])
        : "r"(a0), "r"(a1), "r"(a2), "r"(a3), "r"(b0), "r"(b1));
}

// ---------------------------------------------------------------------------
// Tensor-core transform: per CTA 128 nodes (M) x 128 outs (N = Y|R), K=64.
// 3-term bf16 split: D = Xh*Wh + Xh*Wl + Xl*Wh, fp32 register accumulators.
// Y and R both written as fp16 (half2 pairs); R gets +bias (in fp32) first.
__global__ __launch_bounds__(256)
void transform_mma_kernel(const float4* __restrict__ X,
                          const float* __restrict__ b,
                          int layer, int use_h)
{
    extern __shared__ __nv_bfloat16 sm[];
    __nv_bfloat16* Ah = sm;
    __nv_bfloat16* Al = sm + 128 * PITCH;
    __nv_bfloat16* Bh = sm + 2 * 128 * PITCH;
    __nv_bfloat16* Bl = sm + 3 * 128 * PITCH;

    const int tid = threadIdx.x;
    const int node0 = blockIdx.x * 128;
    const float4* Xv = use_h ? (const float4*)g_h4 : X;

    // Load + split X tile (128 rows x 16 float4 chunks)
    #pragma unroll
    for (int i = tid; i < 2048; i += 256) {
        int n = i >> 4, c = i & 15;
        int gn = node0 + n;
        float4 v = make_float4(0.f, 0.f, 0.f, 0.f);
        if (gn < N_NODES) v = __ldg(Xv + (size_t)gn * 16 + c);
        __nv_bfloat16 hx = __float2bfloat16(v.x), hy = __float2bfloat16(v.y);
        __nv_bfloat16 hz = __float2bfloat16(v.z), hw = __float2bfloat16(v.w);
        __nv_bfloat162 h01, h23, l01, l23;
        h01.x = hx; h01.y = hy; h23.x = hz; h23.y = hw;
        l01.x = __float2bfloat16(v.x - __bfloat162float(hx));
        l01.y = __float2bfloat16(v.y - __bfloat162float(hy));
        l23.x = __float2bfloat16(v.z - __bfloat162float(hz));
        l23.y = __float2bfloat16(v.w - __bfloat162float(hw));
        int base = n * PITCH + c * 4;
        *(__nv_bfloat162*)(Ah + base)     = h01;
        *(__nv_bfloat162*)(Ah + base + 2) = h23;
        *(__nv_bfloat162*)(Al + base)     = l01;
        *(__nv_bfloat162*)(Al + base + 2) = l23;
    }

    // Copy pre-split weights into pitched smem
    {
        const uint32_t* bhp = (const uint32_t*)g_Bh[layer];
        const uint32_t* blp = (const uint32_t*)g_Bl[layer];
        #pragma unroll
        for (int i = tid; i < 4096; i += 256) {
            int n = i >> 5, kp = (i & 31) * 2;
            *(uint32_t*)(Bh + n * PITCH + kp) = __ldg(bhp + i);
            *(uint32_t*)(Bl + n * PITCH + kp) = __ldg(blp + i);
        }
    }
    __syncthreads();

    const int w = tid >> 5, lane = tid & 31;
    const int g = lane >> 2, t = lane & 3;

    float acc[16][4];
    #pragma unroll
    for (int nt = 0; nt < 16; nt++)
        #pragma unroll
        for (int j = 0; j < 4; j++) acc[nt][j] = 0.f;

    const __nv_bfloat16* Aterm[3] = {Ah, Ah, Al};
    const __nv_bfloat16* Bterm[3] = {Bh, Bl, Bh};

    #pragma unroll
    for (int term = 0; term < 3; term++) {
        const __nv_bfloat16* A_ = Aterm[term];
        const __nv_bfloat16* B_ = Bterm[term];
        #pragma unroll
        for (int kk = 0; kk < 4; kk++) {
            const __nv_bfloat16* ar = A_ + (w * 16 + g) * PITCH + kk * 16 + t * 2;
            uint32_t a0 = *(const uint32_t*)ar;
            uint32_t a1 = *(const uint32_t*)(ar + 8 * PITCH);
            uint32_t a2 = *(const uint32_t*)(ar + 8);
            uint32_t a3 = *(const uint32_t*)(ar + 8 * PITCH + 8);
            #pragma unroll
            for (int nt = 0; nt < 16; nt++) {
                const __nv_bfloat16* br = B_ + (nt * 8 + g) * PITCH + kk * 16 + t * 2;
                uint32_t b0 = *(const uint32_t*)br;
                uint32_t b1 = *(const uint32_t*)(br + 8);
                mma16816(acc[nt], a0, a1, a2, a3, b0, b1);
            }
        }
    }

    // Epilogue: c0,c1 -> (row g, cols t*2..+1); c2,c3 -> (row g+8)
    const int row0 = node0 + w * 16 + g;
    const int row1 = row0 + 8;
    uint32_t* Yh = (uint32_t*)g_y4u;      // half2 slots, 32 per node
    uint32_t* Rh = (uint32_t*)g_r4u;      // half2 slots, 32 per node
    #pragma unroll
    for (int nt = 0; nt < 16; nt++) {
        int col = nt * 8 + t * 2;
        if (nt < 8) {
            int hslot = col >> 1;         // = nt*4 + t
            __half2 h01 = __floats2half2_rn(acc[nt][0], acc[nt][1]);
            __half2 h23 = __floats2half2_rn(acc[nt][2], acc[nt][3]);
            if (row0 < N_NODES) Yh[(size_t)row0 * 32 + hslot] = *(uint32_t*)&h01;
            if (row1 < N_NODES) Yh[(size_t)row1 * 32 + hslot] = *(uint32_t*)&h23;
        } else {
            int rc = col - 64;
            int hslot = rc >> 1;
            float2 bb = __ldg((const float2*)(b + rc));
            __half2 h01 = __floats2half2_rn(acc[nt][0] + bb.x, acc[nt][1] + bb.y);
            __half2 h23 = __floats2half2_rn(acc[nt][2] + bb.x, acc[nt][3] + bb.y);
            if (row0 < N_NODES) Rh[(size_t)row0 * 32 + hslot] = *(uint32_t*)&h01;
            if (row1 < N_NODES) Rh[(size_t)row1 * 32 + hslot] = *(uint32_t*)&h23;
        }
    }
}

// ---------------------------------------------------------------------------
// Gather-aggregate + combine. 8 lanes per node, 8 columns (one uint4 of fp16).
// QUAD edge processing: 1 int4 index load + 4 row loads + 2-level HADD2 tree
// (12 HADD2 + 8 cvt + 8 FADD per 4 edges). Scalar head/tail for alignment.
// Layer 1 re-zeroes hist/scanpub for the next graph replay.
__global__ __launch_bounds__(256) void gather_combine_kernel(
    float4* __restrict__ Out, int layer)
{
    int idx = blockIdx.x * 256 + threadIdx.x;   // exactly N_NODES*8
    int n = idx >> 3;
    int c = idx & 7;
    int beg = __ldg(&g_off[n]);
    int end = __ldg(&g_off[n + 1]);

    float a0 = 0.f, a1 = 0.f, a2 = 0.f, a3 = 0.f;
    float a4 = 0.f, a5 = 0.f, a6 = 0.f, a7 = 0.f;

    int e = beg;
    // scalar head until e is 4-aligned (int4 index loads need 16B alignment)
    while ((e & 3) && e < end) {
        int s = __ldg(&g_srcsorted[e]);
        uint4 u = __ldg(&g_y4u[s * 8 + c]);
        float2 f0 = __half22float2(*(__half2*)&u.x);
        float2 f1 = __half22float2(*(__half2*)&u.y);
        float2 f2 = __half22float2(*(__half2*)&u.z);
        float2 f3 = __half22float2(*(__half2*)&u.w);
        a0 += f0.x; a1 += f0.y; a2 += f1.x; a3 += f1.y;
        a4 += f2.x; a5 += f2.y; a6 += f3.x; a7 += f3.y;
        e++;
    }
    // quad loop: 2-level fp16 tree sum, then one fp32 accumulate
    for (; e + 4 <= end; e += 4) {
        int4 ss = __ldg((const int4*)(g_srcsorted + e));
        uint4 u0 = __ldg(&g_y4u[ss.x * 8 + c]);
        uint4 u1 = __ldg(&g_y4u[ss.y * 8 + c]);
        uint4 u2 = __ldg(&g_y4u[ss.z * 8 + c]);
        uint4 u3 = __ldg(&g_y4u[ss.w * 8 + c]);
        __half2 q0 = __hadd2(__hadd2(*(__half2*)&u0.x, *(__half2*)&u1.x),
                             __hadd2(*(__half2*)&u2.x, *(__half2*)&u3.x));
        __half2 q1 = __hadd2(__hadd2(*(__half2*)&u0.y, *(__half2*)&u1.y),
                             __hadd2(*(__half2*)&u2.y, *(__half2*)&u3.y));
        __half2 q2 = __hadd2(__hadd2(*(__half2*)&u0.z, *(__half2*)&u1.z),
                             __hadd2(*(__half2*)&u2.z, *(__half2*)&u3.z));
        __half2 q3 = __hadd2(__hadd2(*(__half2*)&u0.w, *(__half2*)&u1.w),
                             __hadd2(*(__half2*)&u2.w, *(__half2*)&u3.w));
        float2 f0 = __half22float2(q0);
        float2 f1 = __half22float2(q1);
        float2 f2 = __half22float2(q2);
        float2 f3 = __half22float2(q3);
        a0 += f0.x; a1 += f0.y; a2 += f1.x; a3 += f1.y;
        a4 += f2.x; a5 += f2.y; a6 += f3.x; a7 += f3.y;
    }
    // scalar tail
    for (; e < end; e++) {
        int s = __ldg(&g_srcsorted[e]);
        uint4 u = __ldg(&g_y4u[s * 8 + c]);
        float2 f0 = __half22float2(*(__half2*)&u.x);
        float2 f1 = __half22float2(*(__half2*)&u.y);
        float2 f2 = __half22float2(*(__half2*)&u.z);
        float2 f3 = __half22float2(*(__half2*)&u.w);
        a0 += f0.x; a1 += f0.y; a2 += f1.x; a3 += f1.y;
        a4 += f2.x; a5 += f2.y; a6 += f3.x; a7 += f3.y;
    }

    float invd = 1.f / fmaxf((float)(end - beg), 1.f);
    uint4 ru = __ldg(&g_r4u[n * 8 + c]);
    float2 r0 = __half22float2(*(__half2*)&ru.x);
    float2 r1 = __half22float2(*(__half2*)&ru.y);
    float2 r2 = __half22float2(*(__half2*)&ru.z);
    float2 r3 = __half22float2(*(__half2*)&ru.w);
    float4 o0 = make_float4(a0 * invd + r0.x, a1 * invd + r0.y,
                            a2 * invd + r1.x, a3 * invd + r1.y);
    float4 o1 = make_float4(a4 * invd + r2.x, a5 * invd + r2.y,
                            a6 * invd + r3.x, a7 * invd + r3.y);
    if (layer == 1) {
        o0.x = fmaxf(o0.x, 0.f); o0.y = fmaxf(o0.y, 0.f);
        o0.z = fmaxf(o0.z, 0.f); o0.w = fmaxf(o0.w, 0.f);
        o1.x = fmaxf(o1.x, 0.f); o1.y = fmaxf(o1.y, 0.f);
        o1.z = fmaxf(o1.z, 0.f); o1.w = fmaxf(o1.w, 0.f);
        g_h4[n * 16 + c * 2]     = o0;
        g_h4[n * 16 + c * 2 + 1] = o1;
        if (c == 0) g_hist[n] = 0;
        if (blockIdx.x == 0 && threadIdx.x < NB_SCAN) g_scanpub[threadIdx.x] = 0;
    } else {
        Out[n * 16 + c * 2]     = o0;
        Out[n * 16 + c * 2 + 1] = o1;
    }
}

// ---------------------------------------------------------------------------
extern "C" void kernel_launch(void* const* d_in, const int* in_sizes, int n_in,
                              void* d_out, int out_size) {
    const float* x   = (const float*)d_in[0];
    const void*  ei  = d_in[1];
    const float* W1l = (const float*)d_in[2];
    const float* b1  = (const float*)d_in[3];
    const float* W1r = (const float*)d_in[4];
    const float* W2l = (const float*)d_in[5];
    const float* b2  = (const float*)d_in[6];
    const float* W2r = (const float*)d_in[7];

    const int SMEM_BYTES = 4 * 128 * PITCH * 2;   // 73728
    static cudaStream_t s2 = nullptr;
    static cudaEvent_t evFork = nullptr, evJoin = nullptr;
    if (!s2) {
        cudaStreamCreateWithFlags(&s2, cudaStreamNonBlocking);
        cudaEventCreateWithFlags(&evFork, cudaEventDisableTiming);
        cudaEventCreateWithFlags(&evJoin, cudaEventDisableTiming);
        cudaFuncSetAttribute(transform_mma_kernel,
                             cudaFuncAttributeMaxDynamicSharedMemorySize, SMEM_BYTES);
    }

    const int GG = (N_NODES * 8) / 256;     // 3125 (exact)

    // Fork: weight prep + layer-1 transform concurrent with edge sort.
    cudaEventRecord(evFork, 0);
    cudaStreamWaitEvent(s2, evFork, 0);
    prep_w_kernel<<<64, 256, 0, s2>>>(W1l, W1r, W2l, W2r);
    transform_mma_kernel<<<TC_BLOCKS, 256, SMEM_BYTES, s2>>>((const float4*)x, b1, 0, 0);
    cudaEventRecord(evJoin, s2);

    // Edge sort pipeline (stream 0); hist/scanpub zeroed by prior gather L1
    hist_kernel<<<N_EDGES / 1024, 256>>>(ei);          // 1250 blocks
    scan_kernel<<<NB_SCAN, 256>>>();
    place_kernel<<<N_EDGES / 1024, 256>>>(ei);         // 1250 blocks, atomic-free

    // Join, then aggregate
    cudaStreamWaitEvent(0, evJoin, 0);
    gather_combine_kernel<<<GG, 256>>>(nullptr, 1);

    // Layer 2
    transform_mma_kernel<<<TC_BLOCKS, 256, SMEM_BYTES>>>(nullptr, b2, 1, 1);
    gather_combine_kernel<<<GG, 256>>>((float4*)d_out, 2);
}